// round 2
// baseline (speedup 1.0000x reference)
#include <cuda_runtime.h>
#include <math.h>

#define DT_STEP 0.1f
#define EPS_TAU 1e-6f

constexpr int B = 256, T = 512, I = 64, H = 512, O = 64;
constexpr int GRID = 144;  // <= 148 SMs -> all CTAs co-resident (persistent kernel)

// Double-buffered hidden states + barrier state (scratch via __device__ globals).
__device__ float g_h0[2][B * H];
__device__ float g_h1[2][B * H];
__device__ unsigned g_arrive;
__device__ volatile unsigned g_release;

__global__ void k_init() {
    int idx = blockIdx.x * blockDim.x + threadIdx.x;
    if (idx < B * H) {
        g_h0[0][idx] = 0.0f;
        g_h1[0][idx] = 0.0f;
    }
    if (idx == 0) {
        g_arrive = 0;
        g_release = 0;
    }
}

// Software grid barrier: ticket arrive + monotone epoch release.
// __threadfence() (gpu scope) both orders and flushes/invalidates L1D on sm_103a.
__device__ __forceinline__ void gsync(unsigned& epoch) {
    epoch++;
    __syncthreads();
    __threadfence();
    if (threadIdx.x == 0) {
        unsigned ticket = atomicAdd(&g_arrive, 1u) + 1u;
        if (ticket == (unsigned)GRID * epoch) {
            g_release = epoch;
        } else {
            while (g_release < epoch) {
            }
        }
    }
    __syncthreads();
    __threadfence();
}

// Accumulate a 32x32 output tile of Am(row-major, lda) * Wm^T (Wm row-major, ldw)
// over K into per-thread 2x2 accumulators. 256 threads.
__device__ __forceinline__ void mm_acc(float acc[4],
                                       const float* Am, int lda,
                                       const float* Wm, int ldw,
                                       int K,
                                       float (*sa)[33], float (*sw)[33]) {
    const int tid = threadIdx.x;
    const int lr = tid >> 3;          // 0..31 (tile row for loading)
    const int lc = (tid & 7) << 2;    // 0,4,...,28 (k-offset for loading)
    const int ty2 = (tid >> 4) << 1;  // output row pair
    const int tx2 = (tid & 15) << 1;  // output col pair

    for (int k0 = 0; k0 < K; k0 += 32) {
        __syncthreads();
        float4 av = *reinterpret_cast<const float4*>(Am + lr * lda + k0 + lc);
        float4 wv = *reinterpret_cast<const float4*>(Wm + lr * ldw + k0 + lc);
        sa[lc + 0][lr] = av.x; sa[lc + 1][lr] = av.y;
        sa[lc + 2][lr] = av.z; sa[lc + 3][lr] = av.w;
        sw[lc + 0][lr] = wv.x; sw[lc + 1][lr] = wv.y;
        sw[lc + 2][lr] = wv.z; sw[lc + 3][lr] = wv.w;
        __syncthreads();
#pragma unroll
        for (int k = 0; k < 32; k++) {
            float a0 = sa[k][ty2], a1 = sa[k][ty2 + 1];
            float w0 = sw[k][tx2], w1 = sw[k][tx2 + 1];
            acc[0] = fmaf(a0, w0, acc[0]);
            acc[1] = fmaf(a0, w1, acc[1]);
            acc[2] = fmaf(a1, w0, acc[2]);
            acc[3] = fmaf(a1, w1, acc[3]);
        }
    }
}

// One persistent kernel runs the whole T-step scan.
// Per step t:
//   phase A: CTAs 0..127  -> layer-0 Euler update tile (K = H + I)
//            CTAs 128..143-> y(t-1) = h1 @ W_out^T + b_out  (K = H)
//   [grid barrier]
//   phase B: CTAs 0..127  -> layer-1 Euler update tile (K = 2H, both dots fused)
//   [grid barrier]
// Epilogue: CTAs 128..143 emit y(T-1).
__global__ __launch_bounds__(256, 1) void k_scan(
    const float* __restrict__ x, const float* __restrict__ Win0,
    const float* __restrict__ bin0, const float* __restrict__ A0,
    const float* __restrict__ tau0, const float* __restrict__ Win1,
    const float* __restrict__ bin1, const float* __restrict__ A1,
    const float* __restrict__ tau1, const float* __restrict__ Wout,
    const float* __restrict__ bout, float* __restrict__ out) {
    __shared__ float sa[32][33];
    __shared__ float sw[32][33];
    const int tid = threadIdx.x;
    const int ty2 = (tid >> 4) << 1;
    const int tx2 = (tid & 15) << 1;
    const int bx = blockIdx.x;
    unsigned epoch = 0;

    for (int t = 0; t < T; t++) {
        const int pr = t & 1;
        const int pw = pr ^ 1;

        // ---------------- phase A ----------------
        if (bx < 128) {
            const int row0 = (bx >> 4) * 32;  // batch tile
            const int col0 = (bx & 15) * 32;  // hidden tile
            const float* h0r = g_h0[pr];
            float acc[4] = {0.f, 0.f, 0.f, 0.f};
            mm_acc(acc, h0r + row0 * H, H, A0 + col0 * H, H, H, sa, sw);
            mm_acc(acc, x + (row0 * T + t) * I, T * I, Win0 + col0 * I, I, I, sa, sw);
#pragma unroll
            for (int i = 0; i < 2; i++)
#pragma unroll
                for (int j = 0; j < 2; j++) {
                    int b = row0 + ty2 + i;
                    int c = col0 + tx2 + j;
                    float s = acc[i * 2 + j] + bin0[c];
                    float hp = h0r[b * H + c];
                    float itau = 1.0f / (fabsf(tau0[c]) + EPS_TAU);
                    g_h0[pw][b * H + c] = hp + DT_STEP * itau * (tanhf(s) - hp);
                }
        } else if (t > 0) {
            const int idx = bx - 128;          // 0..15
            const int row0 = (idx >> 1) * 32;  // batch tile
            const int col0 = (idx & 1) * 32;   // output tile
            const float* h1r = g_h1[pr];       // h1 of step t-1
            float acc[4] = {0.f, 0.f, 0.f, 0.f};
            mm_acc(acc, h1r + row0 * H, H, Wout + col0 * H, H, H, sa, sw);
#pragma unroll
            for (int i = 0; i < 2; i++)
#pragma unroll
                for (int j = 0; j < 2; j++) {
                    int b = row0 + ty2 + i;
                    int c = col0 + tx2 + j;
                    out[(b * T + (t - 1)) * O + c] = acc[i * 2 + j] + bout[c];
                }
        }
        gsync(epoch);

        // ---------------- phase B ----------------
        if (bx < 128) {
            const int row0 = (bx >> 4) * 32;
            const int col0 = (bx & 15) * 32;
            const float* h0n = g_h0[pw];  // written in phase A this step
            const float* h1r = g_h1[pr];
            float acc[4] = {0.f, 0.f, 0.f, 0.f};
            mm_acc(acc, h0n + row0 * H, H, Win1 + col0 * H, H, H, sa, sw);
            mm_acc(acc, h1r + row0 * H, H, A1 + col0 * H, H, H, sa, sw);
#pragma unroll
            for (int i = 0; i < 2; i++)
#pragma unroll
                for (int j = 0; j < 2; j++) {
                    int b = row0 + ty2 + i;
                    int c = col0 + tx2 + j;
                    float s = acc[i * 2 + j] + bin1[c];
                    float hp = h1r[b * H + c];
                    float itau = 1.0f / (fabsf(tau1[c]) + EPS_TAU);
                    g_h1[pw][b * H + c] = hp + DT_STEP * itau * (tanhf(s) - hp);
                }
        }
        gsync(epoch);
    }

    // ---------------- epilogue: y(T-1) ----------------
    if (bx >= 128) {
        const int idx = bx - 128;
        const int row0 = (idx >> 1) * 32;
        const int col0 = (idx & 1) * 32;
        const float* h1r = g_h1[0];  // step T-1 wrote pw = 0
        float acc[4] = {0.f, 0.f, 0.f, 0.f};
        mm_acc(acc, h1r + row0 * H, H, Wout + col0 * H, H, H, sa, sw);
#pragma unroll
        for (int i = 0; i < 2; i++)
#pragma unroll
            for (int j = 0; j < 2; j++) {
                int b = row0 + ty2 + i;
                int c = col0 + tx2 + j;
                out[(b * T + (T - 1)) * O + c] = acc[i * 2 + j] + bout[c];
            }
    }
}

extern "C" void kernel_launch(void* const* d_in, const int* in_sizes, int n_in,
                              void* d_out, int out_size) {
    const float* x    = (const float*)d_in[0];
    const float* Win0 = (const float*)d_in[1];
    const float* bin0 = (const float*)d_in[2];
    const float* A0   = (const float*)d_in[3];
    const float* tau0 = (const float*)d_in[4];
    const float* Win1 = (const float*)d_in[5];
    const float* bin1 = (const float*)d_in[6];
    const float* A1   = (const float*)d_in[7];
    const float* tau1 = (const float*)d_in[8];
    const float* Wout = (const float*)d_in[9];
    const float* bout = (const float*)d_in[10];
    float* out = (float*)d_out;

    k_init<<<(B * H + 255) / 256, 256>>>();
    k_scan<<<GRID, 256>>>(x, Win0, bin0, A0, tau0, Win1, bin1, A1, tau1,
                          Wout, bout, out);
}

// round 3
// speedup vs baseline: 2.4676x; 2.4676x over previous
#include <cuda_runtime.h>
#include <math.h>

#define DT_STEP 0.1f
#define EPS_TAU 1e-6f

constexpr int B = 256, T = 512, I = 64, H = 512, O = 64;
constexpr int GRID = 144;   // 128 layer CTAs + 16 output-projection CTAs; all co-resident
constexpr int KA = H + I;   // 576  (layer-0: recurrent + input proj)
constexpr int KB = 2 * H;   // 1024 (layer-1: drive + recurrent, fused)
constexpr int SAS = 34;     // activation smem stride (8B-aligned rows, low conflict)

constexpr int SMEM_FLOATS = KA * 32 + KB * 32 + 2 * 32 * SAS + 128;
constexpr int SMEM_BYTES = SMEM_FLOATS * 4;  // ~214 KB

__device__ float g_h0[2][B * H];
__device__ float g_h1[2][B * H];
__device__ unsigned g_arrive;
__device__ volatile unsigned g_release;

__global__ void k_init() {
    int idx = blockIdx.x * blockDim.x + threadIdx.x;
    if (idx < B * H) {
        g_h0[0][idx] = 0.0f;
        g_h1[0][idx] = 0.0f;
    }
    if (idx == 0) {
        g_arrive = 0;
        g_release = 0;
    }
}

// Grid barrier: ticket arrive + monotone epoch release. __threadfence() (gpu
// scope) orders traffic and invalidates L1D (CCTL.IVALL) so cross-CTA hidden
// state reads are not stale. Smem (weights) is unaffected by the flush.
__device__ __forceinline__ void gsync(unsigned& epoch) {
    epoch++;
    __syncthreads();
    __threadfence();
    if (threadIdx.x == 0) {
        unsigned ticket = atomicAdd(&g_arrive, 1u) + 1u;
        if (ticket == (unsigned)GRID * epoch) {
            g_release = epoch;
        } else {
            while (g_release < epoch) {
            }
        }
    }
    __syncthreads();
    __threadfence();
}

// One K-segment of the 32x32-tile GEMM: acc += act(32 rows x K) * Wseg^T.
// Weights already smem-resident in [k][32] layout. Activations streamed
// from global, double-buffered (register prefetch + 2 smem buffers, one
// bar.sync per 32-k tile). 'buf' parity persists across calls, which keeps
// the single-sync-per-tile scheme safe across segment boundaries.
__device__ __forceinline__ void gemm_seg(float acc[4],
                                         const float* __restrict__ src,
                                         int rowStride, int kTiles,
                                         const float* __restrict__ wseg,
                                         float* __restrict__ actb, int& buf) {
    const int tid = threadIdx.x;
    const int lr = tid >> 3;          // staging row 0..31
    const int lc4 = (tid & 7) << 2;   // staging k offset 0,4,...,28
    const int ty2 = (tid >> 4) << 1;  // output row pair
    const int tx2 = (tid & 15) << 1;  // output col pair

    float4 v = *reinterpret_cast<const float4*>(src + lr * rowStride + lc4);
    for (int kt = 0; kt < kTiles; kt++) {
        float* sb = actb + (buf & 1) * (32 * SAS);
        sb[(lc4 + 0) * SAS + lr] = v.x;
        sb[(lc4 + 1) * SAS + lr] = v.y;
        sb[(lc4 + 2) * SAS + lr] = v.z;
        sb[(lc4 + 3) * SAS + lr] = v.w;
        __syncthreads();
        if (kt + 1 < kTiles)
            v = *reinterpret_cast<const float4*>(src + lr * rowStride +
                                                 (kt + 1) * 32 + lc4);
        const float* wk = wseg + kt * (32 * 32) + tx2;
        const float* ar = sb + ty2;
#pragma unroll
        for (int k = 0; k < 32; k++) {
            float2 a = *reinterpret_cast<const float2*>(ar + k * SAS);
            float2 w = *reinterpret_cast<const float2*>(wk + k * 32);
            acc[0] = fmaf(a.x, w.x, acc[0]);
            acc[1] = fmaf(a.x, w.y, acc[1]);
            acc[2] = fmaf(a.y, w.x, acc[2]);
            acc[3] = fmaf(a.y, w.y, acc[3]);
        }
        buf ^= 1;
    }
}

// Persistent kernel: whole T=512 scan, weights staged to smem ONCE.
// Per step t:
//   phase A: CTAs 0..127  -> h0 Euler update (K = 576)
//            CTAs 128..143-> y(t-1) = h1 @ Wout^T + bout (K = 512)
//   [grid barrier]
//   phase B: CTAs 0..127  -> h1 Euler update (K = 1024, both dots fused)
//   [grid barrier]
__global__ __launch_bounds__(256, 1) void k_scan(
    const float* __restrict__ x, const float* __restrict__ Win0,
    const float* __restrict__ bin0, const float* __restrict__ A0,
    const float* __restrict__ tau0, const float* __restrict__ Win1,
    const float* __restrict__ bin1, const float* __restrict__ A1,
    const float* __restrict__ tau1, const float* __restrict__ Wout,
    const float* __restrict__ bout, float* __restrict__ out) {
    extern __shared__ float smem[];
    float* wA = smem;                      // [KA][32]  (y-CTAs: Wout [H][32])
    float* wB = smem + KA * 32;            // [KB][32]
    float* actb = wB + KB * 32;            // [2][32][SAS]
    float* misc = actb + 2 * 32 * SAS;     // biases / inv-tau per col tile

    const int tid = threadIdx.x;
    const int bx = blockIdx.x;
    const int ty2 = (tid >> 4) << 1;
    const int tx2 = (tid & 15) << 1;
    const bool is_main = (bx < 128);
    int row0, col0;
    if (is_main) {
        row0 = (bx >> 4) * 32;
        col0 = (bx & 15) * 32;
    } else {
        int idx = bx - 128;
        row0 = (idx >> 1) * 32;
        col0 = (idx & 1) * 32;
    }

    // ---- one-time weight staging into smem ([k][col] layout) ----
    if (is_main) {
        for (int i = tid; i < H * 32; i += 256) {
            int c = i >> 9, k = i & (H - 1);
            wA[k * 32 + c] = A0[(col0 + c) * H + k];
            wB[k * 32 + c] = Win1[(col0 + c) * H + k];
            wB[(H + k) * 32 + c] = A1[(col0 + c) * H + k];
        }
        for (int i = tid; i < I * 32; i += 256) {
            int c = i >> 6, k = i & (I - 1);
            wA[(H + k) * 32 + c] = Win0[(col0 + c) * I + k];
        }
        if (tid < 32) {
            misc[tid] = bin0[col0 + tid];
            misc[32 + tid] = 1.0f / (fabsf(tau0[col0 + tid]) + EPS_TAU);
            misc[64 + tid] = bin1[col0 + tid];
            misc[96 + tid] = 1.0f / (fabsf(tau1[col0 + tid]) + EPS_TAU);
        }
    } else {
        for (int i = tid; i < H * 32; i += 256) {
            int c = i >> 9, k = i & (H - 1);
            wA[k * 32 + c] = Wout[(col0 + c) * H + k];
        }
        if (tid < 32) misc[tid] = bout[col0 + tid];
    }
    __syncthreads();

    unsigned epoch = 0;
    int buf = 0;

    for (int t = 0; t < T; t++) {
        const int pr = t & 1;
        const int pw = pr ^ 1;

        // ---------------- phase A ----------------
        if (is_main) {
            const float* h0r = g_h0[pr];
            float acc[4] = {0.f, 0.f, 0.f, 0.f};
            gemm_seg(acc, h0r + row0 * H, H, H / 32, wA, actb, buf);
            gemm_seg(acc, x + row0 * (T * I) + t * I, T * I, I / 32,
                     wA + H * 32, actb, buf);
#pragma unroll
            for (int i = 0; i < 2; i++) {
                int gb = row0 + ty2 + i;
                const float* hrow = h0r + gb * H + col0;
                float* wrow = g_h0[pw] + gb * H + col0;
#pragma unroll
                for (int j = 0; j < 2; j++) {
                    int c = tx2 + j;
                    float s = acc[2 * i + j] + misc[c];
                    float hp = hrow[c];
                    wrow[c] = hp + DT_STEP * misc[32 + c] * (tanhf(s) - hp);
                }
            }
        } else if (t > 0) {
            float acc[4] = {0.f, 0.f, 0.f, 0.f};
            gemm_seg(acc, g_h1[pr] + row0 * H, H, H / 32, wA, actb, buf);
#pragma unroll
            for (int i = 0; i < 2; i++) {
                int gb = row0 + ty2 + i;
#pragma unroll
                for (int j = 0; j < 2; j++) {
                    out[gb * (T * O) + (t - 1) * O + col0 + tx2 + j] =
                        acc[2 * i + j] + misc[tx2 + j];
                }
            }
        }
        gsync(epoch);

        // ---------------- phase B ----------------
        if (is_main) {
            const float* h1r = g_h1[pr];
            float acc[4] = {0.f, 0.f, 0.f, 0.f};
            gemm_seg(acc, g_h0[pw] + row0 * H, H, H / 32, wB, actb, buf);
            gemm_seg(acc, h1r + row0 * H, H, H / 32, wB + H * 32, actb, buf);
#pragma unroll
            for (int i = 0; i < 2; i++) {
                int gb = row0 + ty2 + i;
                const float* hrow = h1r + gb * H + col0;
                float* wrow = g_h1[pw] + gb * H + col0;
#pragma unroll
                for (int j = 0; j < 2; j++) {
                    int c = tx2 + j;
                    float s = acc[2 * i + j] + misc[64 + c];
                    float hp = hrow[c];
                    wrow[c] = hp + DT_STEP * misc[96 + c] * (tanhf(s) - hp);
                }
            }
        }
        gsync(epoch);
    }

    // ---------------- epilogue: y(T-1); h1 final lives in buf 0 ----------------
    if (!is_main) {
        float acc[4] = {0.f, 0.f, 0.f, 0.f};
        gemm_seg(acc, g_h1[0] + row0 * H, H, H / 32, wA, actb, buf);
#pragma unroll
        for (int i = 0; i < 2; i++) {
            int gb = row0 + ty2 + i;
#pragma unroll
            for (int j = 0; j < 2; j++) {
                out[gb * (T * O) + (T - 1) * O + col0 + tx2 + j] =
                    acc[2 * i + j] + misc[tx2 + j];
            }
        }
    }
}

extern "C" void kernel_launch(void* const* d_in, const int* in_sizes, int n_in,
                              void* d_out, int out_size) {
    const float* x    = (const float*)d_in[0];
    const float* Win0 = (const float*)d_in[1];
    const float* bin0 = (const float*)d_in[2];
    const float* A0   = (const float*)d_in[3];
    const float* tau0 = (const float*)d_in[4];
    const float* Win1 = (const float*)d_in[5];
    const float* bin1 = (const float*)d_in[6];
    const float* A1   = (const float*)d_in[7];
    const float* tau1 = (const float*)d_in[8];
    const float* Wout = (const float*)d_in[9];
    const float* bout = (const float*)d_in[10];
    float* out = (float*)d_out;

    cudaFuncSetAttribute(k_scan, cudaFuncAttributeMaxDynamicSharedMemorySize,
                         SMEM_BYTES);

    k_init<<<(B * H + 255) / 256, 256>>>();
    k_scan<<<GRID, 256, SMEM_BYTES>>>(x, Win0, bin0, A0, tau0, Win1, bin1, A1,
                                      tau1, Wout, bout, out);
}